// round 8
// baseline (speedup 1.0000x reference)
#include <cuda_runtime.h>
#include <math.h>
#include <stdint.h>

#define T_DEPTH 12
#define E_MSG   8192
#define H_DIM   256
#define V_VOCAB 800
#define B_ROOT  256
#define MAX_NB  8
#define M_TOTAL (T_DEPTH * E_MSG)

#define BM      64
#define PA      260   // sA pitch: bank=(4m+k)%32 conflict-free
#define PB      264   // sB pitch: bank=(8k+n)%32 conflict-free
#define BKK     16
#define N_IT    (H_DIM / BKK)
#define NTHR    512
// smem float counts
#define SM_A_FLOATS   (BM * PA)                 // 16640 per array
#define SM_B_FLOATS   (4 * BKK * PB)            // 2 stages x hi/lo = 16896
#define SM_TOT_FLOATS (2 * SM_A_FLOATS + SM_B_FLOATS)
#define SM_BYTES      (SM_TOT_FLOATS * 4 + (NTHR + BM) * 4)

// Scratch (no cudaMalloc allowed)
__device__ float g_HU[(size_t)(1 + M_TOTAL) * H_DIM];
__device__ float g_EWz0[V_VOCAB * H_DIM];  // emb@Wz0 + bz
__device__ float g_EWr [V_VOCAB * H_DIM];  // emb@Wr + bur
__device__ float g_EWh0[V_VOCAB * H_DIM];  // emb@Wh0 + bh
__device__ float g_EWo0[V_VOCAB * H_DIM];  // emb@Wo0 + bo
// tf32 hi/lo split of depth-invariant B matrices: [0]=Wz1 [1]=Wh1 [2]=Ur, [k][n]
__device__ float g_Bhi[3 * H_DIM * H_DIM];
__device__ float g_Blo[3 * H_DIM * H_DIM];

__device__ __forceinline__ float sigmoidf_(float x) {
    return 1.0f / (1.0f + expf(-x));
}
__device__ __forceinline__ unsigned int tf32_rna(float a) {
    unsigned int r;
    asm("cvt.rna.tf32.f32 %0, %1;" : "=r"(r) : "f"(a));
    return r;
}
__device__ __forceinline__ void mma_tf32(float* d,
                                         unsigned int a0, unsigned int a1,
                                         unsigned int a2, unsigned int a3,
                                         unsigned int b0, unsigned int b1) {
    asm volatile(
        "mma.sync.aligned.m16n8k8.row.col.f32.tf32.tf32.f32 "
        "{%0,%1,%2,%3}, {%4,%5,%6,%7}, {%8,%9}, {%0,%1,%2,%3};"
        : "+f"(d[0]), "+f"(d[1]), "+f"(d[2]), "+f"(d[3])
        : "r"(a0), "r"(a1), "r"(a2), "r"(a3), "r"(b0), "r"(b1));
}
__device__ __forceinline__ void cp_async16(uint32_t saddr, const float* gptr) {
    asm volatile("cp.async.cg.shared.global [%0], [%1], 16;" :: "r"(saddr), "l"(gptr));
}
#define CP_COMMIT()   asm volatile("cp.async.commit_group;")
#define CP_WAIT(n)    asm volatile("cp.async.wait_group %0;" :: "n"(n))

__global__ void zero_kernel(float* __restrict__ h) {
    int j = threadIdx.x;
    h[j] = 0.0f;
    g_HU[j] = 0.0f;
}

// Premultiply embedding by x-side weight blocks; fold biases in.
__global__ void precompute_kernel(const float* __restrict__ emb,
                                  const float* __restrict__ Wz,
                                  const float* __restrict__ Wr,
                                  const float* __restrict__ Wh,
                                  const float* __restrict__ Wo,
                                  const float* __restrict__ bz,
                                  const float* __restrict__ bur,
                                  const float* __restrict__ bh,
                                  const float* __restrict__ bo) {
    __shared__ float se[H_DIM];
    int v = blockIdx.x;
    int j = threadIdx.x;
    se[j] = emb[v * H_DIM + j];
    __syncthreads();
    float az = 0.f, ar = 0.f, ah = 0.f, ao = 0.f;
    #pragma unroll 4
    for (int k = 0; k < H_DIM; k++) {
        float e = se[k];
        az += e * Wz[k * H_DIM + j];
        ar += e * Wr[k * H_DIM + j];
        ah += e * Wh[k * H_DIM + j];
        ao += e * Wo[k * H_DIM + j];
    }
    g_EWz0[v * H_DIM + j] = az + bz[j];
    g_EWr [v * H_DIM + j] = ar + bur[j];
    g_EWh0[v * H_DIM + j] = ah + bh[j];
    g_EWo0[v * H_DIM + j] = ao + bo[j];
}

// Split B matrices (Wz1, Wh1, Ur) into tf32 hi + tf32(residual) tables.
__global__ void bsplit_kernel(const float* __restrict__ Wz,
                              const float* __restrict__ Wh,
                              const float* __restrict__ Ur) {
    int sel = blockIdx.x >> 8;
    int row = blockIdx.x & 255;
    int j   = threadIdx.x;
    const float* src = (sel == 0) ? (Wz + H_DIM * H_DIM)
                     : (sel == 1) ? (Wh + H_DIM * H_DIM) : Ur;
    float w = src[(size_t)row * H_DIM + j];
    unsigned int hi = tf32_rna(w);
    float hif = __uint_as_float(hi);
    unsigned int lo = tf32_rna(w - hif);
    size_t o = (size_t)sel * H_DIM * H_DIM + (size_t)row * H_DIM + j;
    g_Bhi[o] = hif;
    g_Blo[o] = __uint_as_float(lo);
}

// 64x256 GEMM vs one pre-split B table; A resident in smem [64][PA], K=256.
// All 512 threads participate. acc[2][4][4] per thread (warp tile 32x32).
__device__ __forceinline__ void tile_gemm(
    const float* __restrict__ Asm,
    const float* __restrict__ Bhi, const float* __restrict__ Blo,
    float* __restrict__ sB, float acc[2][4][4], int tid) {

    const int lane = tid & 31;
    const int warp = tid >> 5;
    const int wm   = (warp & 1) * 32;
    const int wn   = (warp >> 1) * 32;
    const int g    = lane >> 2;
    const int tig  = lane & 3;

    auto stage = [&](int buf, int kb) {
        #pragma unroll
        for (int cc = 0; cc < 2; cc++) {
            int c  = tid + cc * NTHR;
            int kk = c >> 6;
            int nn = (c & 63) * 4;
            cp_async16((uint32_t)__cvta_generic_to_shared(
                           &sB[(buf * 2 + 0) * BKK * PB + kk * PB + nn]),
                       Bhi + (size_t)(kb + kk) * H_DIM + nn);
            cp_async16((uint32_t)__cvta_generic_to_shared(
                           &sB[(buf * 2 + 1) * BKK * PB + kk * PB + nn]),
                       Blo + (size_t)(kb + kk) * H_DIM + nn);
        }
    };

    stage(0, 0);
    CP_COMMIT();
    int buf = 0;
    for (int it = 0; it < N_IT; it++) {
        if (it + 1 < N_IT) {
            stage(buf ^ 1, (it + 1) * BKK);
            CP_COMMIT();
            CP_WAIT(1);
        } else {
            CP_WAIT(0);
        }
        __syncthreads();

        const float* BH = sB + (buf * 2 + 0) * BKK * PB;
        const float* BL = sB + (buf * 2 + 1) * BKK * PB;
        const int kb = it * BKK;

        #pragma unroll
        for (int ks = 0; ks < BKK; ks += 8) {
            unsigned int ahi[2][4], alo[2][4];
            #pragma unroll
            for (int mf = 0; mf < 2; mf++) {
                const int r0 = wm + mf * 16 + g;
                float a0 = Asm[(r0    ) * PA + kb + ks + tig    ];
                float a1 = Asm[(r0 + 8) * PA + kb + ks + tig    ];
                float a2 = Asm[(r0    ) * PA + kb + ks + tig + 4];
                float a3 = Asm[(r0 + 8) * PA + kb + ks + tig + 4];
                ahi[mf][0] = tf32_rna(a0); alo[mf][0] = tf32_rna(a0 - __uint_as_float(ahi[mf][0]));
                ahi[mf][1] = tf32_rna(a1); alo[mf][1] = tf32_rna(a1 - __uint_as_float(ahi[mf][1]));
                ahi[mf][2] = tf32_rna(a2); alo[mf][2] = tf32_rna(a2 - __uint_as_float(ahi[mf][2]));
                ahi[mf][3] = tf32_rna(a3); alo[mf][3] = tf32_rna(a3 - __uint_as_float(ahi[mf][3]));
            }
            unsigned int bhi[4][2], blo[4][2];
            #pragma unroll
            for (int nf = 0; nf < 4; nf++) {
                const int cc2 = wn + nf * 8 + g;
                bhi[nf][0] = __float_as_uint(BH[(ks + tig    ) * PB + cc2]);
                bhi[nf][1] = __float_as_uint(BH[(ks + tig + 4) * PB + cc2]);
                blo[nf][0] = __float_as_uint(BL[(ks + tig    ) * PB + cc2]);
                blo[nf][1] = __float_as_uint(BL[(ks + tig + 4) * PB + cc2]);
            }
            #pragma unroll
            for (int mf = 0; mf < 2; mf++)
                #pragma unroll
                for (int nf = 0; nf < 4; nf++) {
                    mma_tf32(acc[mf][nf], ahi[mf][0], ahi[mf][1], ahi[mf][2], ahi[mf][3], bhi[nf][0], bhi[nf][1]);
                    mma_tf32(acc[mf][nf], alo[mf][0], alo[mf][1], alo[mf][2], alo[mf][3], bhi[nf][0], bhi[nf][1]);
                    mma_tf32(acc[mf][nf], ahi[mf][0], ahi[mf][1], ahi[mf][2], ahi[mf][3], blo[nf][0], blo[nf][1]);
                }
        }
        __syncthreads();
        buf ^= 1;
    }
}

// ============================================================================
// One kernel per depth: gather -> Z-GEMM -> H-GEMM -> GRU epi -> HU-GEMM.
// Block = 64 full rows (all 256 cols). 512 threads. sumh/sg/new_h in smem.
// ============================================================================
__global__ __launch_bounds__(NTHR, 1) void depth_fused_kernel(
    int t, float* __restrict__ h,
    const int* __restrict__ x_ids, const int* __restrict__ nei_idx) {

    extern __shared__ float smem[];
    float* sA1    = smem;                       // sumh    [64][PA]
    float* sA2    = smem + SM_A_FLOATS;         // sg -> new_h
    float* sB     = smem + 2 * SM_A_FLOATS;     // B staging
    int*   s_nidx = (int*)(smem + SM_TOT_FLOATS);
    int*   s_xid  = s_nidx + NTHR;

    const int tid  = threadIdx.x;
    const int m0   = blockIdx.x * BM;
    const int tE   = t * E_MSG;
    const int base = 1 + tE;

    if (tid < BM) s_xid[tid] = x_ids[tE + m0 + tid];
    s_nidx[tid] = nei_idx[(size_t)(tE + m0) * MAX_NB + tid];   // 512 = 64*8
    __syncthreads();

    // ---- Phase 1: gather (columnwise) into smem ----
    {
        const int col  = tid & 255;
        const int half = tid >> 8;
        #pragma unroll 2
        for (int i = 0; i < 32; i++) {
            const int r = half * 32 + i;
            const int xid = s_xid[r];
            const float r1b = g_EWr[xid * H_DIM + col];   // includes bur
            float sum_h = 0.f, sg = 0.f;
            #pragma unroll
            for (int n = 0; n < MAX_NB; n++) {
                int idx = s_nidx[r * MAX_NB + n];
                if (idx != 0) {
                    float hn = h[(size_t)idx * H_DIM + col];
                    float hu = g_HU[(size_t)idx * H_DIM + col];
                    sum_h += hn;
                    sg = fmaf(sigmoidf_(r1b + hu), hn, sg);
                }
            }
            sA1[r * PA + col] = sum_h;
            sA2[r * PA + col] = sg;
        }
    }
    __syncthreads();

    // ---- Phase 2: Z-GEMM (sumh @ Wz1), H-GEMM (sg @ Wh1) ----
    float accZ[2][4][4], accH[2][4][4];
    #pragma unroll
    for (int mf = 0; mf < 2; mf++)
        #pragma unroll
        for (int nf = 0; nf < 4; nf++)
            #pragma unroll
            for (int c = 0; c < 4; c++) { accZ[mf][nf][c] = 0.f; accH[mf][nf][c] = 0.f; }

    tile_gemm(sA1, g_Bhi,                 g_Blo,                 sB, accZ, tid);
    tile_gemm(sA2, g_Bhi + H_DIM * H_DIM, g_Blo + H_DIM * H_DIM, sB, accH, tid);

    // ---- Phase 3: GRU epilogue; write h and new_h (into sA2) ----
    {
        const int lane = tid & 31;
        const int warp = tid >> 5;
        const int wm   = (warp & 1) * 32;
        const int wn   = (warp >> 1) * 32;
        const int g    = lane >> 2;
        const int tig  = lane & 3;
        #pragma unroll
        for (int mf = 0; mf < 2; mf++)
            #pragma unroll
            for (int hh = 0; hh < 2; hh++) {
                const int rl  = wm + mf * 16 + g + hh * 8;
                const int xid = s_xid[rl];
                #pragma unroll
                for (int nf = 0; nf < 4; nf++) {
                    const int c = wn + nf * 8 + 2 * tig;
                    float2 ewz = *(const float2*)&g_EWz0[(size_t)xid * H_DIM + c];
                    float2 ewh = *(const float2*)&g_EWh0[(size_t)xid * H_DIM + c];
                    float2 sh  = *(const float2*)&sA1[rl * PA + c];
                    float z0 = sigmoidf_(accZ[mf][nf][2 * hh]     + ewz.x);
                    float z1 = sigmoidf_(accZ[mf][nf][2 * hh + 1] + ewz.y);
                    float p0 = tanhf(accH[mf][nf][2 * hh]     + ewh.x);
                    float p1 = tanhf(accH[mf][nf][2 * hh + 1] + ewh.y);
                    float2 o;
                    o.x = (1.f - z0) * sh.x + z0 * p0;
                    o.y = (1.f - z1) * sh.y + z1 * p1;
                    *(float2*)&h[(size_t)(base + m0 + rl) * H_DIM + c] = o;
                    *(float2*)&sA2[rl * PA + c] = o;
                }
            }
    }
    __syncthreads();

    // ---- Phase 4: HU-GEMM (new_h @ Ur) -> g_HU ----
    float accU[2][4][4];
    #pragma unroll
    for (int mf = 0; mf < 2; mf++)
        #pragma unroll
        for (int nf = 0; nf < 4; nf++)
            #pragma unroll
            for (int c = 0; c < 4; c++) accU[mf][nf][c] = 0.f;

    tile_gemm(sA2, g_Bhi + 2 * H_DIM * H_DIM, g_Blo + 2 * H_DIM * H_DIM, sB, accU, tid);

    {
        const int lane = tid & 31;
        const int warp = tid >> 5;
        const int wm   = (warp & 1) * 32;
        const int wn   = (warp >> 1) * 32;
        const int g    = lane >> 2;
        const int tig  = lane & 3;
        #pragma unroll
        for (int mf = 0; mf < 2; mf++) {
            const int r = m0 + wm + mf * 16 + g;
            #pragma unroll
            for (int nf = 0; nf < 4; nf++) {
                const int c = wn + nf * 8 + 2 * tig;
                *(float2*)&g_HU[(size_t)(base + r    ) * H_DIM + c] =
                    make_float2(accU[mf][nf][0], accU[mf][nf][1]);
                *(float2*)&g_HU[(size_t)(base + r + 8) * H_DIM + c] =
                    make_float2(accU[mf][nf][2], accU[mf][nf][3]);
            }
        }
    }
}

// Root aggregation: relu([emb[root_wid], sum_n h[root_nei]] @ Wo + bo)
__global__ void root_kernel(const float* __restrict__ h, float* __restrict__ out2,
                            const int* __restrict__ root_wid,
                            const int* __restrict__ root_nei,
                            const float* __restrict__ Wo) {
    __shared__ float s_sum[H_DIM];
    int b = blockIdx.x, j = threadIdx.x;
    float sum = 0.f;
    #pragma unroll
    for (int n = 0; n < MAX_NB; n++) {
        int idx = root_nei[b * MAX_NB + n];
        if (idx != 0) sum += h[(size_t)idx * H_DIM + j];
    }
    s_sum[j] = sum;
    __syncthreads();
    float acc = g_EWo0[root_wid[b] * H_DIM + j];   // includes bo
    const float* Wo1 = Wo + H_DIM * H_DIM;
    #pragma unroll 4
    for (int k = 0; k < H_DIM; k++) acc += s_sum[k] * Wo1[k * H_DIM + j];
    out2[b * H_DIM + j] = fmaxf(acc, 0.f);
}

extern "C" void kernel_launch(void* const* d_in, const int* in_sizes, int n_in,
                              void* d_out, int out_size) {
    const int*   x_ids    = (const int*)  d_in[0];
    const int*   nei_idx  = (const int*)  d_in[1];
    const int*   root_wid = (const int*)  d_in[2];
    const int*   root_nei = (const int*)  d_in[3];
    const float* emb      = (const float*)d_in[4];
    const float* Wz       = (const float*)d_in[5];
    const float* bz       = (const float*)d_in[6];
    const float* Wr       = (const float*)d_in[7];
    const float* Ur       = (const float*)d_in[8];
    const float* bur      = (const float*)d_in[9];
    const float* Wh       = (const float*)d_in[10];
    const float* bh       = (const float*)d_in[11];
    const float* Wo       = (const float*)d_in[12];
    const float* bo       = (const float*)d_in[13];

    float* h    = (float*)d_out;                         // [(1+M), H]
    float* out2 = h + (size_t)(1 + M_TOTAL) * H_DIM;     // [B, H]

    static bool attr_set = false;
    if (!attr_set) {
        cudaFuncSetAttribute(depth_fused_kernel,
                             cudaFuncAttributeMaxDynamicSharedMemorySize, SM_BYTES);
        attr_set = true;
    }

    zero_kernel<<<1, H_DIM>>>(h);
    precompute_kernel<<<V_VOCAB, H_DIM>>>(emb, Wz, Wr, Wh, Wo, bz, bur, bh, bo);
    bsplit_kernel<<<3 * H_DIM, H_DIM>>>(Wz, Wh, Ur);

    for (int t = 0; t < T_DEPTH; t++) {
        depth_fused_kernel<<<E_MSG / BM, NTHR, SM_BYTES>>>(t, h, x_ids, nei_idx);
    }
    root_kernel<<<B_ROOT, H_DIM>>>(h, out2, root_wid, root_nei, Wo);
}

// round 10
// speedup vs baseline: 1.1396x; 1.1396x over previous
#include <cuda_runtime.h>
#include <math.h>
#include <stdint.h>

#define T_DEPTH 12
#define E_MSG   8192
#define H_DIM   256
#define V_VOCAB 800
#define B_ROOT  256
#define MAX_NB  8
#define M_TOTAL (T_DEPTH * E_MSG)

#define BM   64
#define BN   64
#define BKC  16                   // k per chunk
#define N_CH (H_DIM / BKC)        // 16 chunks
#define AFRAG_FLOATS 4096         // [mfidx4][s2][hl2][lane32][4]
#define BFRAG_FLOATS 2048         // per table: [s2][f8][lane32][4]

// Scratch (no cudaMalloc allowed)
__device__ float g_HU[(size_t)(1 + M_TOTAL) * H_DIM];
__device__ float g_EWz0[V_VOCAB * H_DIM];  // emb@Wz0 + bz
__device__ float g_EWr [V_VOCAB * H_DIM];  // emb@Wr + bur
__device__ float g_EWh0[V_VOCAB * H_DIM];  // emb@Wh0 + bh
__device__ float g_EWo0[V_VOCAB * H_DIM];  // emb@Wo0 + bo
__device__ float g_sumh[(size_t)E_MSG * H_DIM];
__device__ float g_sg  [(size_t)E_MSG * H_DIM];
// fragment-layout pre-split B tables: [tab3][s32][f32][lane32][4]  (hi0,hi1,lo0,lo1)
__device__ float g_Bfrag[(size_t)3 * 32 * 32 * 32 * 4];

__device__ __forceinline__ float sigmoidf_(float x) {
    return 1.0f / (1.0f + expf(-x));
}
__device__ __forceinline__ unsigned int tf32_rna(float a) {
    unsigned int r;
    asm("cvt.rna.tf32.f32 %0, %1;" : "=r"(r) : "f"(a));
    return r;
}
__device__ __forceinline__ void mma_tf32(float* d,
                                         unsigned int a0, unsigned int a1,
                                         unsigned int a2, unsigned int a3,
                                         unsigned int b0, unsigned int b1) {
    asm volatile(
        "mma.sync.aligned.m16n8k8.row.col.f32.tf32.tf32.f32 "
        "{%0,%1,%2,%3}, {%4,%5,%6,%7}, {%8,%9}, {%0,%1,%2,%3};"
        : "+f"(d[0]), "+f"(d[1]), "+f"(d[2]), "+f"(d[3])
        : "r"(a0), "r"(a1), "r"(a2), "r"(a3), "r"(b0), "r"(b1));
}
__device__ __forceinline__ void cp_async16(uint32_t saddr, const float* gptr) {
    asm volatile("cp.async.cg.shared.global [%0], [%1], 16;" :: "r"(saddr), "l"(gptr));
}
#define CP_COMMIT()   asm volatile("cp.async.commit_group;")
#define CP_WAIT(n)    asm volatile("cp.async.wait_group %0;" :: "n"(n))

__global__ void zero_kernel(float* __restrict__ h) {
    int j = threadIdx.x;
    h[j] = 0.0f;
    g_HU[j] = 0.0f;
}

// Premultiply embedding by x-side weight blocks; fold biases in.
__global__ void precompute_kernel(const float* __restrict__ emb,
                                  const float* __restrict__ Wz,
                                  const float* __restrict__ Wr,
                                  const float* __restrict__ Wh,
                                  const float* __restrict__ Wo,
                                  const float* __restrict__ bz,
                                  const float* __restrict__ bur,
                                  const float* __restrict__ bh,
                                  const float* __restrict__ bo) {
    __shared__ float se[H_DIM];
    int v = blockIdx.x;
    int j = threadIdx.x;
    se[j] = emb[v * H_DIM + j];
    __syncthreads();
    float az = 0.f, ar = 0.f, ah = 0.f, ao = 0.f;
    #pragma unroll 4
    for (int k = 0; k < H_DIM; k++) {
        float e = se[k];
        az += e * Wz[k * H_DIM + j];
        ar += e * Wr[k * H_DIM + j];
        ah += e * Wh[k * H_DIM + j];
        ao += e * Wo[k * H_DIM + j];
    }
    g_EWz0[v * H_DIM + j] = az + bz[j];
    g_EWr [v * H_DIM + j] = ar + bur[j];
    g_EWh0[v * H_DIM + j] = ah + bh[j];
    g_EWo0[v * H_DIM + j] = ao + bo[j];
}

// Pre-split B (Wz1, Wh1, Ur) into mma-fragment layout with tf32 hi/lo per lane.
// blk = sel*32 + s. Each (f,lane) slot holds [hi(k=tig), hi(k=tig+4), lo, lo].
__global__ void bsplit_frag_kernel(const float* __restrict__ Wz,
                                   const float* __restrict__ Wh,
                                   const float* __restrict__ Ur) {
    int blk = blockIdx.x;
    int sel = blk >> 5, s = blk & 31;
    const float* src = (sel == 0) ? (Wz + H_DIM * H_DIM)
                     : (sel == 1) ? (Wh + H_DIM * H_DIM) : Ur;
    int tid = threadIdx.x;
    #pragma unroll
    for (int i = 0; i < 4; i++) {
        int p  = tid + i * 256;          // 0..1023
        int f  = p >> 5, ln = p & 31;
        int tg = ln & 3,  gg = ln >> 2;
        int k0 = s * 8 + tg, n = f * 8 + gg;
        float w0 = src[(size_t)k0 * H_DIM + n];
        float w1 = src[(size_t)(k0 + 4) * H_DIM + n];
        float4 v;
        v.x = __uint_as_float(tf32_rna(w0));
        v.y = __uint_as_float(tf32_rna(w1));
        v.z = __uint_as_float(tf32_rna(w0 - v.x));
        v.w = __uint_as_float(tf32_rna(w1 - v.y));
        *(float4*)&g_Bfrag[((((size_t)sel * 32 + s) * 32 + f) * 32 + ln) * 4] = v;
    }
}

// Phase A: neighbor gather. One block per message; thread j = column j.
__global__ __launch_bounds__(H_DIM) void gather_kernel(
    int t, const float* __restrict__ h,
    const int* __restrict__ x_ids, const int* __restrict__ nei_idx) {

    __shared__ int s_nidx[MAX_NB];
    const int e = blockIdx.x;
    const int j = threadIdx.x;

    if (j < MAX_NB)
        s_nidx[j] = nei_idx[((size_t)(t * E_MSG + e)) * MAX_NB + j];
    __syncthreads();

    const int xid = x_ids[t * E_MSG + e];
    const float r1b = g_EWr[xid * H_DIM + j];   // includes bur

    float sum_h = 0.f, sg = 0.f;
    #pragma unroll
    for (int n = 0; n < MAX_NB; n++) {
        int idx = s_nidx[n];
        if (idx != 0) {
            float hn = h[(size_t)idx * H_DIM + j];
            float hu = g_HU[(size_t)idx * H_DIM + j];
            sum_h += hn;
            sg = fmaf(sigmoidf_(r1b + hu), hn, sg);
        }
    }
    g_sumh[(size_t)e * H_DIM + j] = sum_h;
    g_sg  [(size_t)e * H_DIM + j] = sg;
}

// ---- A staging helpers (fragment layout, hi/lo pre-split) ----
// Element (row r 0..63, klocal 0..15) of chunk -> frag slot.
__device__ __forceinline__ void sts_a_frag(float* aBase, int r, int klocal, float v) {
    int s    = klocal >> 3;
    int kk   = klocal & 7;
    int tg   = kk & 3;
    int ch   = kk >> 2;
    int ln   = ((r & 7) << 2) | tg;
    int slot = ((r >> 3) & 1) | (ch << 1);
    int mf   = r >> 4;
    unsigned int hi = tf32_rna(v);
    float hif = __uint_as_float(hi);
    float lof = __uint_as_float(tf32_rna(v - hif));
    aBase[((mf * 2 + s) * 2 + 0) * 128 + ln * 4 + slot] = hif;
    aBase[((mf * 2 + s) * 2 + 1) * 128 + ln * 4 + slot] = lof;
}

// ============================================================================
// Dual GEMM (sumh@Wz1, sg@Wh1) + fused GRU epilogue. 64x64 tile, 256 threads.
// A staged pre-split in frag layout; B via cp.async from g_Bfrag.
// ============================================================================
__global__ __launch_bounds__(256, 2) void gemm_zh_epi_kernel(
    int t, float* __restrict__ h,
    const float* __restrict__ sumh, const float* __restrict__ sg,
    const int* __restrict__ x_ids) {

    extern __shared__ float sm[];
    float* sA = sm;                          // [buf2][arr2][AFRAG_FLOATS]
    float* sB = sm + 2 * 2 * AFRAG_FLOATS;   // [buf2][tab2][BFRAG_FLOATS]

    const int tid  = threadIdx.x;
    const int lane = tid & 31;
    const int warp = tid >> 5;
    const int wm   = (warp & 1) * 32;
    const int wn   = (warp >> 1) * 16;
    const int g    = lane >> 2;
    const int tig  = lane & 3;
    const int m0   = blockIdx.x * BM;
    const int n0   = blockIdx.y * BN;
    const int f0   = n0 >> 3;
    const int tE   = t * E_MSG;
    const int base = 1 + tE;

    const int arow = tid >> 2;
    const int akq  = (tid & 3) * 4;

    auto cpB = [&](int buf, int ch) {
        const int s0 = ch * 2;
        #pragma unroll
        for (int i = 0; i < 4; i++) {
            int u    = tid + i * 256;
            int tab  = u >> 9;
            int rem  = u & 511;
            int s    = rem >> 8;
            int rem2 = rem & 255;
            int f    = rem2 >> 5;
            int ln   = rem2 & 31;
            const float* src = &g_Bfrag[((((size_t)tab * 32 + s0 + s) * 32 + f0 + f) * 32 + ln) * 4];
            float* dst = &sB[buf * 2 * BFRAG_FLOATS + tab * BFRAG_FLOATS +
                             ((s * 8 + f) * 32 + ln) * 4];
            cp_async16((uint32_t)__cvta_generic_to_shared(dst), src);
        }
    };
    auto ldgA = [&](int ch, float4& v1, float4& v2) {
        size_t o = (size_t)(m0 + arow) * H_DIM + ch * BKC + akq;
        v1 = *(const float4*)&sumh[o];
        v2 = *(const float4*)&sg[o];
    };
    auto stsA = [&](int buf, float4 v1, float4 v2) {
        float* a1 = &sA[buf * 2 * AFRAG_FLOATS];
        float* a2 = a1 + AFRAG_FLOATS;
        sts_a_frag(a1, arow, akq + 0, v1.x); sts_a_frag(a1, arow, akq + 1, v1.y);
        sts_a_frag(a1, arow, akq + 2, v1.z); sts_a_frag(a1, arow, akq + 3, v1.w);
        sts_a_frag(a2, arow, akq + 0, v2.x); sts_a_frag(a2, arow, akq + 1, v2.y);
        sts_a_frag(a2, arow, akq + 2, v2.z); sts_a_frag(a2, arow, akq + 3, v2.w);
    };

    float accZ[2][2][4], accH[2][2][4];
    #pragma unroll
    for (int mf = 0; mf < 2; mf++)
        #pragma unroll
        for (int nf = 0; nf < 2; nf++)
            #pragma unroll
            for (int c = 0; c < 4; c++) { accZ[mf][nf][c] = 0.f; accH[mf][nf][c] = 0.f; }

    // prolog: stage chunk 0
    {
        float4 v1, v2;
        ldgA(0, v1, v2);
        stsA(0, v1, v2);
        cpB(0, 0);
        CP_COMMIT();
    }

    for (int it = 0; it < N_CH; it++) {
        const int buf = it & 1;
        float4 nv1, nv2;
        if (it + 1 < N_CH) {
            cpB(buf ^ 1, it + 1);
            CP_COMMIT();
            ldgA(it + 1, nv1, nv2);
            CP_WAIT(1);
        } else {
            CP_WAIT(0);
        }
        __syncthreads();

        const float* aBuf = &sA[buf * 2 * AFRAG_FLOATS];
        const float* bBuf = &sB[buf * 2 * BFRAG_FLOATS];

        #pragma unroll
        for (int s = 0; s < 2; s++) {
            #pragma unroll
            for (int arr = 0; arr < 2; arr++) {
                const float* aArr = aBuf + arr * AFRAG_FLOATS;
                const float* bTab = bBuf + arr * BFRAG_FLOATS;
                // B frags for this warp's 16 cols (2 frags of 8)
                uint4 bq[2];
                #pragma unroll
                for (int nf = 0; nf < 2; nf++) {
                    int fl = (wn >> 3) + nf;
                    bq[nf] = *(const uint4*)&bTab[((s * 8 + fl) * 32 + lane) * 4];
                }
                #pragma unroll
                for (int mf = 0; mf < 2; mf++) {
                    int mfidx = (wm >> 4) + mf;
                    uint4 ah = *(const uint4*)&aArr[((mfidx * 2 + s) * 2 + 0) * 128 + lane * 4];
                    uint4 al = *(const uint4*)&aArr[((mfidx * 2 + s) * 2 + 1) * 128 + lane * 4];
                    #pragma unroll
                    for (int nf = 0; nf < 2; nf++) {
                        float* d = (arr == 0) ? accZ[mf][nf] : accH[mf][nf];
                        mma_tf32(d, ah.x, ah.y, ah.z, ah.w, bq[nf].x, bq[nf].y);
                        mma_tf32(d, al.x, al.y, al.z, al.w, bq[nf].x, bq[nf].y);
                        mma_tf32(d, ah.x, ah.y, ah.z, ah.w, bq[nf].z, bq[nf].w);
                    }
                }
            }
        }
        if (it + 1 < N_CH) {
            stsA(buf ^ 1, nv1, nv2);
        }
        __syncthreads();
    }

    // ---- fused GRU epilogue ----
    #pragma unroll
    for (int mf = 0; mf < 2; mf++) {
        #pragma unroll
        for (int hh = 0; hh < 2; hh++) {
            const int row = m0 + wm + mf * 16 + g + hh * 8;
            const int xid = x_ids[tE + row];
            #pragma unroll
            for (int nf = 0; nf < 2; nf++) {
                const int c = n0 + wn + nf * 8 + 2 * tig;
                float az0 = accZ[mf][nf][2 * hh], az1 = accZ[mf][nf][2 * hh + 1];
                float ah0 = accH[mf][nf][2 * hh], ah1 = accH[mf][nf][2 * hh + 1];
                float2 ewz = *(const float2*)&g_EWz0[(size_t)xid * H_DIM + c];
                float2 ewh = *(const float2*)&g_EWh0[(size_t)xid * H_DIM + c];
                float2 sh  = *(const float2*)&sumh[(size_t)row * H_DIM + c];
                float z0 = sigmoidf_(az0 + ewz.x);
                float z1 = sigmoidf_(az1 + ewz.y);
                float p0 = tanhf(ah0 + ewh.x);
                float p1 = tanhf(ah1 + ewh.y);
                float2 out;
                out.x = (1.f - z0) * sh.x + z0 * p0;
                out.y = (1.f - z1) * sh.y + z1 * p1;
                *(float2*)&h[(size_t)(base + row) * H_DIM + c] = out;
            }
        }
    }
}

// ============================================================================
// HU memo GEMM: HU = new_h @ Ur. Single-array variant of the same scheme.
// ============================================================================
__global__ __launch_bounds__(256, 2) void gemm_hu_kernel(
    const float* __restrict__ A, float* __restrict__ C) {

    extern __shared__ float sm[];
    float* sA = sm;                      // [buf2][AFRAG_FLOATS]
    float* sB = sm + 2 * AFRAG_FLOATS;   // [buf2][BFRAG_FLOATS]

    const int tid  = threadIdx.x;
    const int lane = tid & 31;
    const int warp = tid >> 5;
    const int wm   = (warp & 1) * 32;
    const int wn   = (warp >> 1) * 16;
    const int g    = lane >> 2;
    const int tig  = lane & 3;
    const int m0   = blockIdx.x * BM;
    const int n0   = blockIdx.y * BN;
    const int f0   = n0 >> 3;

    const int arow = tid >> 2;
    const int akq  = (tid & 3) * 4;

    auto cpB = [&](int buf, int ch) {
        const int s0 = ch * 2;
        #pragma unroll
        for (int i = 0; i < 2; i++) {
            int u    = tid + i * 256;     // 0..511
            int s    = u >> 8;
            int rem2 = u & 255;
            int f    = rem2 >> 5;
            int ln   = rem2 & 31;
            const float* src = &g_Bfrag[((((size_t)2 * 32 + s0 + s) * 32 + f0 + f) * 32 + ln) * 4];
            float* dst = &sB[buf * BFRAG_FLOATS + ((s * 8 + f) * 32 + ln) * 4];
            cp_async16((uint32_t)__cvta_generic_to_shared(dst), src);
        }
    };

    float acc[2][2][4];
    #pragma unroll
    for (int mf = 0; mf < 2; mf++)
        #pragma unroll
        for (int nf = 0; nf < 2; nf++)
            #pragma unroll
            for (int c = 0; c < 4; c++) acc[mf][nf][c] = 0.f;

    {
        float4 v = *(const float4*)&A[(size_t)(m0 + arow) * H_DIM + akq];
        float* a0 = &sA[0];
        sts_a_frag(a0, arow, akq + 0, v.x); sts_a_frag(a0, arow, akq + 1, v.y);
        sts_a_frag(a0, arow, akq + 2, v.z); sts_a_frag(a0, arow, akq + 3, v.w);
        cpB(0, 0);
        CP_COMMIT();
    }

    for (int it = 0; it < N_CH; it++) {
        const int buf = it & 1;
        float4 nv;
        if (it + 1 < N_CH) {
            cpB(buf ^ 1, it + 1);
            CP_COMMIT();
            nv = *(const float4*)&A[(size_t)(m0 + arow) * H_DIM + (it + 1) * BKC + akq];
            CP_WAIT(1);
        } else {
            CP_WAIT(0);
        }
        __syncthreads();

        const float* aBuf = &sA[buf * AFRAG_FLOATS];
        const float* bBuf = &sB[buf * BFRAG_FLOATS];

        #pragma unroll
        for (int s = 0; s < 2; s++) {
            uint4 bq[2];
            #pragma unroll
            for (int nf = 0; nf < 2; nf++) {
                int fl = (wn >> 3) + nf;
                bq[nf] = *(const uint4*)&bBuf[((s * 8 + fl) * 32 + lane) * 4];
            }
            #pragma unroll
            for (int mf = 0; mf < 2; mf++) {
                int mfidx = (wm >> 4) + mf;
                uint4 ah = *(const uint4*)&aBuf[((mfidx * 2 + s) * 2 + 0) * 128 + lane * 4];
                uint4 al = *(const uint4*)&aBuf[((mfidx * 2 + s) * 2 + 1) * 128 + lane * 4];
                #pragma unroll
                for (int nf = 0; nf < 2; nf++) {
                    mma_tf32(acc[mf][nf], ah.x, ah.y, ah.z, ah.w, bq[nf].x, bq[nf].y);
                    mma_tf32(acc[mf][nf], al.x, al.y, al.z, al.w, bq[nf].x, bq[nf].y);
                    mma_tf32(acc[mf][nf], ah.x, ah.y, ah.z, ah.w, bq[nf].z, bq[nf].w);
                }
            }
        }
        if (it + 1 < N_CH) {
            float* a1 = &sA[(buf ^ 1) * AFRAG_FLOATS];
            sts_a_frag(a1, arow, akq + 0, nv.x); sts_a_frag(a1, arow, akq + 1, nv.y);
            sts_a_frag(a1, arow, akq + 2, nv.z); sts_a_frag(a1, arow, akq + 3, nv.w);
        }
        __syncthreads();
    }

    #pragma unroll
    for (int mf = 0; mf < 2; mf++) {
        const int r = m0 + wm + mf * 16 + g;
        #pragma unroll
        for (int nf = 0; nf < 2; nf++) {
            const int c = n0 + wn + nf * 8 + 2 * tig;
            *(float2*)&C[(size_t)(r    ) * H_DIM + c] = make_float2(acc[mf][nf][0], acc[mf][nf][1]);
            *(float2*)&C[(size_t)(r + 8) * H_DIM + c] = make_float2(acc[mf][nf][2], acc[mf][nf][3]);
        }
    }
}

// Root aggregation: relu([emb[root_wid], sum_n h[root_nei]] @ Wo + bo)
__global__ void root_kernel(const float* __restrict__ h, float* __restrict__ out2,
                            const int* __restrict__ root_wid,
                            const int* __restrict__ root_nei,
                            const float* __restrict__ Wo) {
    __shared__ float s_sum[H_DIM];
    int b = blockIdx.x, j = threadIdx.x;
    float sum = 0.f;
    #pragma unroll
    for (int n = 0; n < MAX_NB; n++) {
        int idx = root_nei[b * MAX_NB + n];
        if (idx != 0) sum += h[(size_t)idx * H_DIM + j];
    }
    s_sum[j] = sum;
    __syncthreads();
    float acc = g_EWo0[root_wid[b] * H_DIM + j];   // includes bo
    const float* Wo1 = Wo + H_DIM * H_DIM;
    #pragma unroll 4
    for (int k = 0; k < H_DIM; k++) acc += s_sum[k] * Wo1[k * H_DIM + j];
    out2[b * H_DIM + j] = fmaxf(acc, 0.f);
}

extern "C" void kernel_launch(void* const* d_in, const int* in_sizes, int n_in,
                              void* d_out, int out_size) {
    const int*   x_ids    = (const int*)  d_in[0];
    const int*   nei_idx  = (const int*)  d_in[1];
    const int*   root_wid = (const int*)  d_in[2];
    const int*   root_nei = (const int*)  d_in[3];
    const float* emb      = (const float*)d_in[4];
    const float* Wz       = (const float*)d_in[5];
    const float* bz       = (const float*)d_in[6];
    const float* Wr       = (const float*)d_in[7];
    const float* Ur       = (const float*)d_in[8];
    const float* bur      = (const float*)d_in[9];
    const float* Wh       = (const float*)d_in[10];
    const float* bh       = (const float*)d_in[11];
    const float* Wo       = (const float*)d_in[12];
    const float* bo       = (const float*)d_in[13];

    float* h    = (float*)d_out;                         // [(1+M), H]
    float* out2 = h + (size_t)(1 + M_TOTAL) * H_DIM;     // [B, H]

    float *p_sumh, *p_sg, *p_HU;
    cudaGetSymbolAddress((void**)&p_sumh, g_sumh);
    cudaGetSymbolAddress((void**)&p_sg,   g_sg);
    cudaGetSymbolAddress((void**)&p_HU,   g_HU);

    const int zh_smem = (2 * 2 * AFRAG_FLOATS + 2 * 2 * BFRAG_FLOATS) * (int)sizeof(float); // 96 KB
    const int hu_smem = (2 * AFRAG_FLOATS + 2 * BFRAG_FLOATS) * (int)sizeof(float);          // 48 KB
    static bool attr_set = false;
    if (!attr_set) {
        cudaFuncSetAttribute(gemm_zh_epi_kernel,
                             cudaFuncAttributeMaxDynamicSharedMemorySize, zh_smem);
        cudaFuncSetAttribute(gemm_hu_kernel,
                             cudaFuncAttributeMaxDynamicSharedMemorySize, hu_smem);
        attr_set = true;
    }

    zero_kernel<<<1, H_DIM>>>(h);
    precompute_kernel<<<V_VOCAB, H_DIM>>>(emb, Wz, Wr, Wh, Wo, bz, bur, bh, bo);
    bsplit_frag_kernel<<<96, 256>>>(Wz, Wh, Ur);

    dim3 ggrid(E_MSG / BM, H_DIM / BN);
    for (int t = 0; t < T_DEPTH; t++) {
        const size_t base = (size_t)(1 + t * E_MSG) * H_DIM;
        gather_kernel<<<E_MSG, H_DIM>>>(t, h, x_ids, nei_idx);
        gemm_zh_epi_kernel<<<ggrid, 256, zh_smem>>>(t, h, p_sumh, p_sg, x_ids);
        gemm_hu_kernel<<<ggrid, 256, hu_smem>>>(h + base, p_HU + base);
    }
    root_kernel<<<B_ROOT, H_DIM>>>(h, out2, root_wid, root_nei, Wo);
}